// round 2
// baseline (speedup 1.0000x reference)
#include <cuda_runtime.h>
#include <cuda_bf16.h>

// Problem constants
#define BATCH 4
#define TDIM  4096
#define DM    1024
#define HH    16
#define NTOK  (BATCH*TDIM)        // 16384 tokens
#define NCOMB 160                 // 96 skew cols + 64 v cols
#define NCHAIN (BATCH*HH)         // 64 scan chains
#define CHUNK 32
#define NCHUNK (TDIM/CHUNK)       // 128 chunks per chain

// Scratch (device globals: allocation-free contract)
__device__ __align__(16) float g_comb[NTOK * NCOMB];          // 10.5 MB: [bt][160]
__device__ __align__(16) float g_O[NCHAIN * TDIM * 16];       // 16.8 MB: [chain][t][16]
__device__ __align__(16) float g_tot[NCHAIN * NCHUNK * 16];   // chunk totals
__device__ __align__(16) float g_pre[NCHAIN * NCHUNK * 16];   // exclusive chunk prefixes
__device__ __align__(16) float g_rot[NTOK * 64];              // 4 MB: [bt][h*4+i]

// ---------------------------------------------------------------------------
// 4x4 row-major matmul: C = A @ B
// ---------------------------------------------------------------------------
__device__ __forceinline__ void mm4(const float* __restrict__ A,
                                    const float* __restrict__ B,
                                    float* __restrict__ C) {
#pragma unroll
    for (int i = 0; i < 4; i++) {
#pragma unroll
        for (int j = 0; j < 4; j++) {
            C[i*4+j] = fmaf(A[i*4+0], B[0*4+j],
                       fmaf(A[i*4+1], B[1*4+j],
                       fmaf(A[i*4+2], B[2*4+j],
                            A[i*4+3] * B[3*4+j])));
        }
    }
}

__device__ __forceinline__ void load16(float* dst, const float* src) {
    const float4* s = (const float4*)src;
    float4* d = (float4*)dst;
    d[0] = s[0]; d[1] = s[1]; d[2] = s[2]; d[3] = s[3];
}
__device__ __forceinline__ void store16(float* dst, const float* src) {
    load16(dst, src);
}

// ---------------------------------------------------------------------------
// GEMM1: comb[bt, 0:96]  = x[bt,:] @ W_skew   (1024 x 96)
//        comb[bt, 96:160]= x[bt,:] @ W_v      (1024 x 64)
// Block: 64 tokens x 160 cols.  256 threads, 4x10 microtile each.
// ---------------------------------------------------------------------------
__global__ void __launch_bounds__(256) gemm_in_kernel(
    const float* __restrict__ x,
    const float* __restrict__ Ws,
    const float* __restrict__ Wv)
{
    __shared__ float xs[64][33];       // pad to kill bank conflicts
    __shared__ float ws[32][NCOMB];    // 20 KB

    const int m0 = blockIdx.x * 64;
    const int tid = threadIdx.x;
    const int rowg = tid >> 4;   // 0..15
    const int colg = tid & 15;   // 0..15

    float acc[4][10];
#pragma unroll
    for (int i = 0; i < 4; i++)
#pragma unroll
        for (int j = 0; j < 10; j++) acc[i][j] = 0.0f;

    for (int k0 = 0; k0 < DM; k0 += 32) {
        // load x tile: 64 rows x 32 k  (2048 floats, 8 per thread, coalesced)
#pragma unroll
        for (int i = 0; i < 8; i++) {
            int idx = tid + i * 256;
            int r = idx >> 5, k = idx & 31;
            xs[r][k] = x[(size_t)(m0 + r) * DM + k0 + k];
        }
        // load W tile: 32 k x 160 cols (5120 floats, 20 per thread)
#pragma unroll
        for (int i = 0; i < 20; i++) {
            int idx = tid + i * 256;
            int k = idx / NCOMB, c = idx % NCOMB;
            float v = (c < 96) ? Ws[(size_t)(k0 + k) * 96 + c]
                               : Wv[(size_t)(k0 + k) * 64 + (c - 96)];
            ws[k][c] = v;
        }
        __syncthreads();

#pragma unroll
        for (int k = 0; k < 32; k++) {
            float a[4], b[10];
#pragma unroll
            for (int i = 0; i < 4; i++) a[i] = xs[rowg * 4 + i][k];
#pragma unroll
            for (int j = 0; j < 10; j++) b[j] = ws[k][colg * 10 + j];
#pragma unroll
            for (int i = 0; i < 4; i++)
#pragma unroll
                for (int j = 0; j < 10; j++)
                    acc[i][j] = fmaf(a[i], b[j], acc[i][j]);
        }
        __syncthreads();
    }

#pragma unroll
    for (int i = 0; i < 4; i++)
#pragma unroll
        for (int j = 0; j < 10; j++)
            g_comb[(size_t)(m0 + rowg * 4 + i) * NCOMB + colg * 10 + j] = acc[i][j];
}

// ---------------------------------------------------------------------------
// expm of 4x4 skew-symmetric, one thread per (bt, h).
// Scaling & squaring + 10-term Horner Taylor.
// ---------------------------------------------------------------------------
__global__ void __launch_bounds__(256) expm_kernel()
{
    int idx = blockIdx.x * blockDim.x + threadIdx.x;   // 262144
    int bt = idx >> 4;
    int h  = idx & 15;

    const float* f = &g_comb[(size_t)bt * NCOMB + h * 6];
    float a0 = f[0], a1 = f[1], a2 = f[2], a3 = f[3], a4 = f[4], a5 = f[5];

    float A[16] = {  0.f,  a0,  a1,  a2,
                    -a0, 0.f,  a3,  a4,
                    -a1, -a3, 0.f,  a5,
                    -a2, -a4, -a5, 0.f };

    float r0 = fabsf(a0) + fabsf(a1) + fabsf(a2);
    float r1 = fabsf(a0) + fabsf(a3) + fabsf(a4);
    float r2 = fabsf(a1) + fabsf(a3) + fabsf(a5);
    float r3 = fabsf(a2) + fabsf(a4) + fabsf(a5);
    float nrm = fmaxf(fmaxf(r0, r1), fmaxf(r2, r3));

    int s = 0;
    while (nrm > 0.5f && s < 40) { nrm *= 0.5f; s++; }
    float sc = exp2f((float)(-s));
#pragma unroll
    for (int e = 0; e < 16; e++) A[e] *= sc;

    // Horner Taylor: P = I + A(I + A/2 (I + A/3 (... (I + A/10))))
    float P[16];
#pragma unroll
    for (int e = 0; e < 16; e++) P[e] = (e % 5 == 0) ? 1.0f : 0.0f;

#pragma unroll
    for (int k = 10; k >= 1; --k) {
        float Tm[16];
        mm4(A, P, Tm);
        float inv = 1.0f / (float)k;
#pragma unroll
        for (int e = 0; e < 16; e++)
            P[e] = Tm[e] * inv + ((e % 5 == 0) ? 1.0f : 0.0f);
    }
    // repeated squaring
    for (int i = 0; i < s; i++) {
        float Tm[16];
        mm4(P, P, Tm);
#pragma unroll
        for (int e = 0; e < 16; e++) P[e] = Tm[e];
    }

    int b = bt >> 12;            // /TDIM
    int t = bt & (TDIM - 1);
    int chain = b * HH + h;
    store16(&g_O[((size_t)chain * TDIM + t) * 16], P);
}

// ---------------------------------------------------------------------------
// Scan pass 1: per (chain, chunk) compute chunk total product
//   Tot = O_{t1} @ ... @ O_{t0}
// ---------------------------------------------------------------------------
__global__ void __launch_bounds__(128) scan_chunks_kernel()
{
    int g = blockIdx.x * blockDim.x + threadIdx.x;  // 8192
    int chain = g >> 7;     // /NCHUNK
    int chunk = g & (NCHUNK - 1);

    float P[16];
#pragma unroll
    for (int e = 0; e < 16; e++) P[e] = (e % 5 == 0) ? 1.0f : 0.0f;

    const float* base = &g_O[((size_t)chain * TDIM + chunk * CHUNK) * 16];
    for (int l = 0; l < CHUNK; l++) {
        float M[16], Tm[16];
        load16(M, base + l * 16);
        mm4(M, P, Tm);
#pragma unroll
        for (int e = 0; e < 16; e++) P[e] = Tm[e];
    }
    store16(&g_tot[((size_t)chain * NCHUNK + chunk) * 16], P);
}

// ---------------------------------------------------------------------------
// Scan pass 2: one WARP per chain; 16 lanes each own one element of the
// running exclusive prefix E. Step: E_new = Tot_c @ E via shuffles.
//   pre[c] = Tot_{c-1} @ ... @ Tot_0   (pre[0] = I)
// Lane l owns element (i,j) with i = l>>2, j = l&3.
// (Tot@E)[i][j] = sum_k Tot[i][k] * E[k][j]
//   Tot[i][k] lives in lane i*4+k, E[k][j] lives in lane k*4+j.
// ---------------------------------------------------------------------------
__global__ void __launch_bounds__(256) scan_tops_kernel()
{
    int warp = (blockIdx.x * blockDim.x + threadIdx.x) >> 5;
    int lane = threadIdx.x & 31;
    if (warp >= NCHAIN || lane >= 16) return;
    const int chain = warp;
    const int i = lane >> 2, j = lane & 3;

    float E = (i == j) ? 1.0f : 0.0f;    // this lane's element of prefix

    const unsigned mask = 0x0000FFFFu;
    for (int c = 0; c < NCHUNK; c++) {
        g_pre[((size_t)chain * NCHUNK + c) * 16 + lane] = E;
        float tot = g_tot[((size_t)chain * NCHUNK + c) * 16 + lane];  // Tot[i][j]
        float acc = 0.0f;
#pragma unroll
        for (int k = 0; k < 4; k++) {
            float t_ik = __shfl_sync(mask, tot, i * 4 + k, 32);
            float e_kj = __shfl_sync(mask, E,   k * 4 + j, 32);
            acc = fmaf(t_ik, e_kj, acc);
        }
        E = acc;
    }
}

// ---------------------------------------------------------------------------
// Scan pass 3: re-walk chunk, apply prefix, rotate v.
//   rotated[t] = L_t @ (Pex @ v[t])
// ---------------------------------------------------------------------------
__global__ void __launch_bounds__(128) scan_apply_kernel()
{
    int g = blockIdx.x * blockDim.x + threadIdx.x;  // 8192
    int chain = g >> 7;
    int chunk = g & (NCHUNK - 1);
    int b = chain >> 4, h = chain & 15;

    float Pex[16];
    load16(Pex, &g_pre[((size_t)chain * NCHUNK + chunk) * 16]);

    float L[16];
#pragma unroll
    for (int e = 0; e < 16; e++) L[e] = (e % 5 == 0) ? 1.0f : 0.0f;

    for (int l = 0; l < CHUNK; l++) {
        int t = chunk * CHUNK + l;
        float M[16], Tm[16];
        load16(M, &g_O[((size_t)chain * TDIM + t) * 16]);
        mm4(M, L, Tm);
#pragma unroll
        for (int e = 0; e < 16; e++) L[e] = Tm[e];

        size_t bt = (size_t)b * TDIM + t;
        float4 v4 = *(const float4*)&g_comb[bt * NCOMB + 96 + h * 4];

        float w0 = fmaf(Pex[0], v4.x, fmaf(Pex[1], v4.y, fmaf(Pex[2],  v4.z, Pex[3]  * v4.w)));
        float w1 = fmaf(Pex[4], v4.x, fmaf(Pex[5], v4.y, fmaf(Pex[6],  v4.z, Pex[7]  * v4.w)));
        float w2 = fmaf(Pex[8], v4.x, fmaf(Pex[9], v4.y, fmaf(Pex[10], v4.z, Pex[11] * v4.w)));
        float w3 = fmaf(Pex[12],v4.x, fmaf(Pex[13],v4.y, fmaf(Pex[14], v4.z, Pex[15] * v4.w)));

        float r0g = fmaf(L[0], w0, fmaf(L[1], w1, fmaf(L[2],  w2, L[3]  * w3)));
        float r1g = fmaf(L[4], w0, fmaf(L[5], w1, fmaf(L[6],  w2, L[7]  * w3)));
        float r2g = fmaf(L[8], w0, fmaf(L[9], w1, fmaf(L[10], w2, L[11] * w3)));
        float r3g = fmaf(L[12],w0, fmaf(L[13],w1, fmaf(L[14], w2, L[15] * w3)));

        *(float4*)&g_rot[bt * 64 + h * 4] = make_float4(r0g, r1g, r2g, r3g);
    }
}

// ---------------------------------------------------------------------------
// GEMM out: out[bt, c] = rotated[bt, :64] @ W_o[:64, c]
// Block: 64 tokens x 64 cols, 256 threads, 4x4 microtile.
// ---------------------------------------------------------------------------
__global__ void __launch_bounds__(256) gemm_out_kernel(
    const float* __restrict__ Wo,
    float* __restrict__ out)
{
    __shared__ float rs[64][65];
    __shared__ float ws[64][64];

    const int m0 = blockIdx.x * 64;
    const int c0 = blockIdx.y * 64;
    const int tid = threadIdx.x;

#pragma unroll
    for (int i = 0; i < 16; i++) {
        int idx = tid + i * 256;
        int r = idx >> 6, k = idx & 63;
        rs[r][k] = g_rot[(size_t)(m0 + r) * 64 + k];
    }
#pragma unroll
    for (int i = 0; i < 16; i++) {
        int idx = tid + i * 256;
        int k = idx >> 6, c = idx & 63;
        ws[k][c] = Wo[(size_t)k * DM + c0 + c];
    }
    __syncthreads();

    const int rowg = tid >> 4, colg = tid & 15;
    float acc[4][4];
#pragma unroll
    for (int i = 0; i < 4; i++)
#pragma unroll
        for (int j = 0; j < 4; j++) acc[i][j] = 0.0f;

#pragma unroll
    for (int k = 0; k < 64; k++) {
        float a[4];
#pragma unroll
        for (int i = 0; i < 4; i++) a[i] = rs[rowg * 4 + i][k];
        float4 b4 = *(const float4*)&ws[k][colg * 4];
#pragma unroll
        for (int i = 0; i < 4; i++) {
            acc[i][0] = fmaf(a[i], b4.x, acc[i][0]);
            acc[i][1] = fmaf(a[i], b4.y, acc[i][1]);
            acc[i][2] = fmaf(a[i], b4.z, acc[i][2]);
            acc[i][3] = fmaf(a[i], b4.w, acc[i][3]);
        }
    }

#pragma unroll
    for (int i = 0; i < 4; i++) {
        *(float4*)&out[(size_t)(m0 + rowg * 4 + i) * DM + c0 + colg * 4] =
            make_float4(acc[i][0], acc[i][1], acc[i][2], acc[i][3]);
    }
}

// ---------------------------------------------------------------------------
extern "C" void kernel_launch(void* const* d_in, const int* in_sizes, int n_in,
                              void* d_out, int out_size)
{
    const float* x  = (const float*)d_in[0];
    const float* Ws = (const float*)d_in[1];
    const float* Wv = (const float*)d_in[2];
    const float* Wo = (const float*)d_in[3];
    float* out = (float*)d_out;

    gemm_in_kernel<<<NTOK / 64, 256>>>(x, Ws, Wv);
    expm_kernel<<<(NTOK * HH) / 256, 256>>>();
    scan_chunks_kernel<<<(NCHAIN * NCHUNK) / 128, 128>>>();
    scan_tops_kernel<<<(NCHAIN * 32) / 256, 256>>>();
    scan_apply_kernel<<<(NCHAIN * NCHUNK) / 128, 128>>>();
    gemm_out_kernel<<<dim3(NTOK / 64, DM / 64), 256>>>(Wo, out);
}

// round 3
// speedup vs baseline: 1.1287x; 1.1287x over previous
#include <cuda_runtime.h>
#include <cuda_bf16.h>

// Problem constants
#define BATCH 4
#define TDIM  4096
#define DM    1024
#define HH    16
#define NTOK  (BATCH*TDIM)        // 16384 tokens
#define NCOMB 160                 // 96 skew cols + 64 v cols
#define NCHAIN (BATCH*HH)         // 64 scan chains
#define CHUNK 32
#define NCHUNK (TDIM/CHUNK)       // 128 chunks per chain

typedef unsigned long long u64;

// Scratch (device globals: allocation-free contract)
__device__ __align__(16) float g_comb[NTOK * NCOMB];          // 10.5 MB
__device__ __align__(16) float g_O[NCHAIN * TDIM * 16];       // 16.8 MB
__device__ __align__(16) float g_tot[NCHAIN * NCHUNK * 16];   // chunk totals
__device__ __align__(16) float g_pre[NCHAIN * NCHUNK * 16];   // exclusive chunk prefixes
__device__ __align__(16) float g_rot[NTOK * 64];              // 4 MB

// ---------------------------------------------------------------------------
// Packed fp32x2 helpers (Blackwell dual-FMA path; ptxas won't emit from C++)
// ---------------------------------------------------------------------------
__device__ __forceinline__ u64 pack2(float lo, float hi) {
    u64 d;
    asm("mov.b64 %0, {%1, %2};" : "=l"(d) : "r"(__float_as_uint(lo)), "r"(__float_as_uint(hi)));
    return d;
}
__device__ __forceinline__ u64 fma2(u64 a, u64 b, u64 c) {
    u64 d;
    asm("fma.rn.f32x2 %0, %1, %2, %3;" : "=l"(d) : "l"(a), "l"(b), "l"(c));
    return d;
}
__device__ __forceinline__ void unpack2(u64 v, float& lo, float& hi) {
    unsigned ulo, uhi;
    asm("mov.b64 {%0, %1}, %2;" : "=r"(ulo), "=r"(uhi) : "l"(v));
    lo = __uint_as_float(ulo); hi = __uint_as_float(uhi);
}

// ---------------------------------------------------------------------------
// 4x4 row-major matmul: C = A @ B
// ---------------------------------------------------------------------------
__device__ __forceinline__ void mm4(const float* __restrict__ A,
                                    const float* __restrict__ B,
                                    float* __restrict__ C) {
#pragma unroll
    for (int i = 0; i < 4; i++) {
#pragma unroll
        for (int j = 0; j < 4; j++) {
            C[i*4+j] = fmaf(A[i*4+0], B[0*4+j],
                       fmaf(A[i*4+1], B[1*4+j],
                       fmaf(A[i*4+2], B[2*4+j],
                            A[i*4+3] * B[3*4+j])));
        }
    }
}

__device__ __forceinline__ void load16(float* dst, const float* src) {
    const float4* s = (const float4*)src;
    float4* d = (float4*)dst;
    d[0] = s[0]; d[1] = s[1]; d[2] = s[2]; d[3] = s[3];
}
__device__ __forceinline__ void store16(float* dst, const float* src) {
    load16(dst, src);
}

// ---------------------------------------------------------------------------
// GEMM1: comb[bt, 0:96]  = x[bt,:] @ W_skew   (1024 x 96)
//        comb[bt, 96:160]= x[bt,:] @ W_v      (1024 x 64)
// Block: 64 tokens x 160 cols. 256 threads, 4x10 microtile via 4x5 f32x2.
// ---------------------------------------------------------------------------
__global__ void __launch_bounds__(256) gemm_in_kernel(
    const float* __restrict__ x,
    const float* __restrict__ Ws,
    const float* __restrict__ Wv)
{
    __shared__ __align__(16) float xs[64][33];       // pad to kill bank conflicts
    __shared__ __align__(16) float ws[32][NCOMB];    // 20 KB

    const int m0 = blockIdx.x * 64;
    const int tid = threadIdx.x;
    const int rowg = tid >> 4;   // 0..15
    const int colg = tid & 15;   // 0..15

    u64 acc[4][5];
#pragma unroll
    for (int i = 0; i < 4; i++)
#pragma unroll
        for (int j = 0; j < 5; j++) acc[i][j] = 0ULL;   // (+0.0f, +0.0f)

    for (int k0 = 0; k0 < DM; k0 += 32) {
        // load x tile: 64 rows x 32 k (coalesced)
#pragma unroll
        for (int i = 0; i < 8; i++) {
            int idx = tid + i * 256;
            int r = idx >> 5, k = idx & 31;
            xs[r][k] = x[(size_t)(m0 + r) * DM + k0 + k];
        }
        // load W tile: 32 k x 160 cols
#pragma unroll
        for (int i = 0; i < 20; i++) {
            int idx = tid + i * 256;
            int k = idx / NCOMB, c = idx % NCOMB;
            float v = (c < 96) ? Ws[(size_t)(k0 + k) * 96 + c]
                               : Wv[(size_t)(k0 + k) * 64 + (c - 96)];
            ws[k][c] = v;
        }
        __syncthreads();

#pragma unroll
        for (int k = 0; k < 32; k++) {
            u64 aa[4];
#pragma unroll
            for (int i = 0; i < 4; i++) {
                float a = xs[rowg * 4 + i][k];
                aa[i] = pack2(a, a);
            }
            // 10 contiguous b floats = 5 aligned LDS.64 (colg*10 floats = 40B, 8B-aligned)
            const u64* bp = (const u64*)&ws[k][colg * 10];
            u64 bb[5];
#pragma unroll
            for (int j = 0; j < 5; j++) bb[j] = bp[j];
#pragma unroll
            for (int i = 0; i < 4; i++)
#pragma unroll
                for (int j = 0; j < 5; j++)
                    acc[i][j] = fma2(aa[i], bb[j], acc[i][j]);
        }
        __syncthreads();
    }

#pragma unroll
    for (int i = 0; i < 4; i++) {
        float* dst = &g_comb[(size_t)(m0 + rowg * 4 + i) * NCOMB + colg * 10];
#pragma unroll
        for (int j = 0; j < 5; j++) {
            float lo, hi;
            unpack2(acc[i][j], lo, hi);
            *(float2*)&dst[2 * j] = make_float2(lo, hi);
        }
    }
}

// ---------------------------------------------------------------------------
// expm of 4x4 skew-symmetric, one thread per (bt, h).
// Scaling & squaring + 10-term Horner Taylor.
// ---------------------------------------------------------------------------
__global__ void __launch_bounds__(256) expm_kernel()
{
    int idx = blockIdx.x * blockDim.x + threadIdx.x;   // 262144
    int bt = idx >> 4;
    int h  = idx & 15;

    const float* f = &g_comb[(size_t)bt * NCOMB + h * 6];
    float a0 = f[0], a1 = f[1], a2 = f[2], a3 = f[3], a4 = f[4], a5 = f[5];

    float A[16] = {  0.f,  a0,  a1,  a2,
                    -a0, 0.f,  a3,  a4,
                    -a1, -a3, 0.f,  a5,
                    -a2, -a4, -a5, 0.f };

    float r0 = fabsf(a0) + fabsf(a1) + fabsf(a2);
    float r1 = fabsf(a0) + fabsf(a3) + fabsf(a4);
    float r2 = fabsf(a1) + fabsf(a3) + fabsf(a5);
    float r3 = fabsf(a2) + fabsf(a4) + fabsf(a5);
    float nrm = fmaxf(fmaxf(r0, r1), fmaxf(r2, r3));

    int s = 0;
    while (nrm > 0.5f && s < 40) { nrm *= 0.5f; s++; }
    float sc = exp2f((float)(-s));
#pragma unroll
    for (int e = 0; e < 16; e++) A[e] *= sc;

    // Horner Taylor: P = I + A(I + A/2 (I + A/3 (... (I + A/10))))
    float P[16];
#pragma unroll
    for (int e = 0; e < 16; e++) P[e] = (e % 5 == 0) ? 1.0f : 0.0f;

#pragma unroll
    for (int k = 10; k >= 1; --k) {
        float Tm[16];
        mm4(A, P, Tm);
        float inv = 1.0f / (float)k;
#pragma unroll
        for (int e = 0; e < 16; e++)
            P[e] = Tm[e] * inv + ((e % 5 == 0) ? 1.0f : 0.0f);
    }
    // repeated squaring
    for (int i = 0; i < s; i++) {
        float Tm[16];
        mm4(P, P, Tm);
#pragma unroll
        for (int e = 0; e < 16; e++) P[e] = Tm[e];
    }

    int b = bt >> 12;            // /TDIM
    int t = bt & (TDIM - 1);
    int chain = b * HH + h;
    store16(&g_O[((size_t)chain * TDIM + t) * 16], P);
}

// ---------------------------------------------------------------------------
// Scan pass 1: per (chain, chunk) compute chunk total product
// ---------------------------------------------------------------------------
__global__ void __launch_bounds__(128) scan_chunks_kernel()
{
    int g = blockIdx.x * blockDim.x + threadIdx.x;  // 8192
    int chain = g >> 7;     // /NCHUNK
    int chunk = g & (NCHUNK - 1);

    float P[16];
#pragma unroll
    for (int e = 0; e < 16; e++) P[e] = (e % 5 == 0) ? 1.0f : 0.0f;

    const float* base = &g_O[((size_t)chain * TDIM + chunk * CHUNK) * 16];
    for (int l = 0; l < CHUNK; l++) {
        float M[16], Tm[16];
        load16(M, base + l * 16);
        mm4(M, P, Tm);
#pragma unroll
        for (int e = 0; e < 16; e++) P[e] = Tm[e];
    }
    store16(&g_tot[((size_t)chain * NCHUNK + chunk) * 16], P);
}

// ---------------------------------------------------------------------------
// Scan pass 2: one BLOCK per chain. 128 threads, thread c holds chunk-total
// matrix c in registers. Kogge-Stone inclusive scan (7 rounds through smem),
// then exclusive shift. Segment product of [a..c] = Tot_c @ ... @ Tot_a, so
// the combine is V_c <- V_c @ V_{c-off}.
// ---------------------------------------------------------------------------
__global__ void __launch_bounds__(128) scan_tops_kernel()
{
    __shared__ float sm[NCHUNK][17];   // 17-pad: odd stride, conflict-free
    const int chain = blockIdx.x;
    const int c = threadIdx.x;

    float V[16];
    load16(V, &g_tot[((size_t)chain * NCHUNK + c) * 16]);

#pragma unroll
    for (int r = 0; r < 7; r++) {
        const int off = 1 << r;
#pragma unroll
        for (int e = 0; e < 16; e++) sm[c][e] = V[e];
        __syncthreads();
        if (c >= off) {
            float U[16], T[16];
#pragma unroll
            for (int e = 0; e < 16; e++) U[e] = sm[c - off][e];
            mm4(V, U, T);
#pragma unroll
            for (int e = 0; e < 16; e++) V[e] = T[e];
        }
        __syncthreads();
    }

    // exclusive shift: pre[c] = inclusive[c-1], pre[0] = I
#pragma unroll
    for (int e = 0; e < 16; e++) sm[c][e] = V[e];
    __syncthreads();
    float P[16];
    if (c == 0) {
#pragma unroll
        for (int e = 0; e < 16; e++) P[e] = (e % 5 == 0) ? 1.0f : 0.0f;
    } else {
#pragma unroll
        for (int e = 0; e < 16; e++) P[e] = sm[c - 1][e];
    }
    store16(&g_pre[((size_t)chain * NCHUNK + c) * 16], P);
}

// ---------------------------------------------------------------------------
// Scan pass 3: re-walk chunk, apply prefix, rotate v.
//   rotated[t] = L_t @ (Pex @ v[t])
// ---------------------------------------------------------------------------
__global__ void __launch_bounds__(128) scan_apply_kernel()
{
    int g = blockIdx.x * blockDim.x + threadIdx.x;  // 8192
    int chain = g >> 7;
    int chunk = g & (NCHUNK - 1);
    int b = chain >> 4, h = chain & 15;

    float Pex[16];
    load16(Pex, &g_pre[((size_t)chain * NCHUNK + chunk) * 16]);

    float L[16];
#pragma unroll
    for (int e = 0; e < 16; e++) L[e] = (e % 5 == 0) ? 1.0f : 0.0f;

    for (int l = 0; l < CHUNK; l++) {
        int t = chunk * CHUNK + l;
        float M[16], Tm[16];
        load16(M, &g_O[((size_t)chain * TDIM + t) * 16]);
        mm4(M, L, Tm);
#pragma unroll
        for (int e = 0; e < 16; e++) L[e] = Tm[e];

        size_t bt = (size_t)b * TDIM + t;
        float4 v4 = *(const float4*)&g_comb[bt * NCOMB + 96 + h * 4];

        float w0 = fmaf(Pex[0], v4.x, fmaf(Pex[1], v4.y, fmaf(Pex[2],  v4.z, Pex[3]  * v4.w)));
        float w1 = fmaf(Pex[4], v4.x, fmaf(Pex[5], v4.y, fmaf(Pex[6],  v4.z, Pex[7]  * v4.w)));
        float w2 = fmaf(Pex[8], v4.x, fmaf(Pex[9], v4.y, fmaf(Pex[10], v4.z, Pex[11] * v4.w)));
        float w3 = fmaf(Pex[12],v4.x, fmaf(Pex[13],v4.y, fmaf(Pex[14], v4.z, Pex[15] * v4.w)));

        float r0g = fmaf(L[0], w0, fmaf(L[1], w1, fmaf(L[2],  w2, L[3]  * w3)));
        float r1g = fmaf(L[4], w0, fmaf(L[5], w1, fmaf(L[6],  w2, L[7]  * w3)));
        float r2g = fmaf(L[8], w0, fmaf(L[9], w1, fmaf(L[10], w2, L[11] * w3)));
        float r3g = fmaf(L[12],w0, fmaf(L[13],w1, fmaf(L[14], w2, L[15] * w3)));

        *(float4*)&g_rot[bt * 64 + h * 4] = make_float4(r0g, r1g, r2g, r3g);
    }
}

// ---------------------------------------------------------------------------
// GEMM out: out[bt, c] = rotated[bt, :64] @ W_o[:64, c]
// Block: 64 tokens x 64 cols, 256 threads. Each thread owns column pairs
// (colg*2, colg*2+1) and (colg*2+32, colg*2+33): LDS.64 at 8B thread stride
// is bank-conflict-free, and pairs map directly onto f32x2 accumulators.
// ---------------------------------------------------------------------------
__global__ void __launch_bounds__(256) gemm_out_kernel(
    const float* __restrict__ Wo,
    float* __restrict__ out)
{
    __shared__ __align__(16) float rs[64][65];
    __shared__ __align__(16) float ws[64][64];

    const int m0 = blockIdx.x * 64;
    const int c0 = blockIdx.y * 64;
    const int tid = threadIdx.x;

#pragma unroll
    for (int i = 0; i < 16; i++) {
        int idx = tid + i * 256;
        int r = idx >> 6, k = idx & 63;
        rs[r][k] = g_rot[(size_t)(m0 + r) * 64 + k];
    }
#pragma unroll
    for (int i = 0; i < 16; i++) {
        int idx = tid + i * 256;
        int k = idx >> 6, c = idx & 63;
        ws[k][c] = Wo[(size_t)k * DM + c0 + c];
    }
    __syncthreads();

    const int rowg = tid >> 4, colg = tid & 15;
    u64 acc[4][2];
#pragma unroll
    for (int i = 0; i < 4; i++) { acc[i][0] = 0ULL; acc[i][1] = 0ULL; }

#pragma unroll
    for (int k = 0; k < 64; k++) {
        u64 b0 = *(const u64*)&ws[k][colg * 2];
        u64 b1 = *(const u64*)&ws[k][colg * 2 + 32];
#pragma unroll
        for (int i = 0; i < 4; i++) {
            float a = rs[rowg * 4 + i][k];
            u64 aa = pack2(a, a);
            acc[i][0] = fma2(aa, b0, acc[i][0]);
            acc[i][1] = fma2(aa, b1, acc[i][1]);
        }
    }

#pragma unroll
    for (int i = 0; i < 4; i++) {
        float lo, hi;
        float* dst = &out[(size_t)(m0 + rowg * 4 + i) * DM + c0];
        unpack2(acc[i][0], lo, hi);
        *(float2*)&dst[colg * 2] = make_float2(lo, hi);
        unpack2(acc[i][1], lo, hi);
        *(float2*)&dst[colg * 2 + 32] = make_float2(lo, hi);
    }
}

// ---------------------------------------------------------------------------
extern "C" void kernel_launch(void* const* d_in, const int* in_sizes, int n_in,
                              void* d_out, int out_size)
{
    const float* x  = (const float*)d_in[0];
    const float* Ws = (const float*)d_in[1];
    const float* Wv = (const float*)d_in[2];
    const float* Wo = (const float*)d_in[3];
    float* out = (float*)d_out;

    gemm_in_kernel<<<NTOK / 64, 256>>>(x, Ws, Wv);
    expm_kernel<<<(NTOK * HH) / 256, 256>>>();
    scan_chunks_kernel<<<(NCHAIN * NCHUNK) / 128, 128>>>();
    scan_tops_kernel<<<NCHAIN, 128>>>();
    scan_apply_kernel<<<(NCHAIN * NCHUNK) / 128, 128>>>();
    gemm_out_kernel<<<dim3(NTOK / 64, DM / 64), 256>>>(Wo, out);
}